// round 1
// baseline (speedup 1.0000x reference)
#include <cuda_runtime.h>
#include <math.h>

// ---------------------------------------------------------------------------
// ControllerLSTM on GB300 — key insight: batch rows are all identical
// (inputs ignored, zero initial state, all ops row-wise), so compute B=1 and
// replicate. 23 sequential LSTM "cells", each a pair of 2048->8192 fp32 GEMVs
// (W_ih on the selected embedding row + W_hh on h), fused LSTM pointwise,
// then a tiny decode GEMV + argmax selecting the next embedding row.
// Single persistent kernel, custom grid barrier (1 per cell).
// ---------------------------------------------------------------------------

#define H     2048
#define BSZ   1024
#define NBK   12
#define NCTA  128
#define NTHR  256
#define NWARP 8
#define TOTW  (NCTA * NWARP)   // 1024 warps, each owns n and n+1024

__device__ float    g_hbuf[2][H];
__device__ float    g_cbuf[H];
__device__ unsigned g_bar_count = 0;
__device__ unsigned g_bar_gen   = 0;

__device__ __forceinline__ void grid_sync() {
    __syncthreads();
    if (threadIdx.x == 0) {
        __threadfence();
        unsigned gen = *((volatile unsigned*)&g_bar_gen);
        if (atomicAdd(&g_bar_count, 1u) == NCTA - 1) {
            *((volatile unsigned*)&g_bar_count) = 0;
            __threadfence();
            atomicAdd(&g_bar_gen, 1u);
        } else {
            while (*((volatile unsigned*)&g_bar_gen) == gen) { __nanosleep(40); }
        }
    }
    __syncthreads();
}

__device__ __forceinline__ float wreduce(float v) {
    #pragma unroll
    for (int o = 16; o > 0; o >>= 1) v += __shfl_xor_sync(0xffffffffu, v, o);
    return v;
}

__device__ __forceinline__ float sigf(float x) { return 1.0f / (1.0f + expf(-x)); }

__global__ __launch_bounds__(NTHR, 1)
void controller_lstm_kernel(
    const float* __restrict__ W_ih,   const float* __restrict__ W_hh,
    const float* __restrict__ b_ih,   const float* __restrict__ b_hh,
    const float* __restrict__ enc_act, const float* __restrict__ enc_block,
    const float* __restrict__ dec_act, const float* __restrict__ dec_block,
    float* __restrict__ out)
{
    __shared__ float h_sm[H];   // previous h (8 KB)
    __shared__ float e_sm[H];   // embedding row (8 KB)
    __shared__ int   idx_sm;

    const int tid  = threadIdx.x;
    const int lane = tid & 31;
    const int wid  = tid >> 5;
    const int cta  = blockIdx.x;
    const int gw   = cta * NWARP + wid;           // global warp id: owns n=gw, n=gw+TOTW

    float cloc0 = 0.0f, cloc1 = 0.0f;             // warp-local cell state (replicated in-warp)
    int   idx   = 0;                              // current discrete selection (per-thread)

    for (int cell = 0; cell < 2 * NBK - 1; cell++) {
        const int wbuf = cell & 1;

        // ---- stage h_prev + embedding row into smem ----
        const float* emb = 0;
        if (cell > 0) {
            const int bid = (cell + 1) >> 1;      // cells 2b-1, 2b belong to block bid=b
            if (cell & 1) emb = enc_act   + ((size_t)(bid - 1) * 4         + idx) * H;
            else          emb = enc_block + ((size_t)(bid - 1) * (NBK - 1) + idx) * H;
            const float4* hp = (const float4*)g_hbuf[wbuf ^ 1];
            const float4* ep = (const float4*)emb;
            for (int i = tid; i < H / 4; i += NTHR) {
                ((float4*)h_sm)[i] = hp[i];
                ((float4*)e_sm)[i] = ep[i];
            }
        }
        __syncthreads();

        // ---- GEMV + fused LSTM pointwise for the two owned n's ----
        #pragma unroll 1
        for (int t = 0; t < 2; t++) {
            const int n = gw + t * TOTW;
            float acc0 = 0.f, acc1 = 0.f, acc2 = 0.f, acc3 = 0.f;
            if (cell > 0) {
                const float4* wi0 = (const float4*)(W_ih + ((size_t)0 * H + n) * H);
                const float4* wi1 = (const float4*)(W_ih + ((size_t)1 * H + n) * H);
                const float4* wi2 = (const float4*)(W_ih + ((size_t)2 * H + n) * H);
                const float4* wi3 = (const float4*)(W_ih + ((size_t)3 * H + n) * H);
                const float4* wh0 = (const float4*)(W_hh + ((size_t)0 * H + n) * H);
                const float4* wh1 = (const float4*)(W_hh + ((size_t)1 * H + n) * H);
                const float4* wh2 = (const float4*)(W_hh + ((size_t)2 * H + n) * H);
                const float4* wh3 = (const float4*)(W_hh + ((size_t)3 * H + n) * H);
                for (int k = lane; k < H / 4; k += 32) {
                    const float4 hv = ((const float4*)h_sm)[k];
                    const float4 ev = ((const float4*)e_sm)[k];
                    float4 a, b;
                    a = wi0[k]; b = wh0[k];
                    acc0 += ev.x*a.x + ev.y*a.y + ev.z*a.z + ev.w*a.w
                          + hv.x*b.x + hv.y*b.y + hv.z*b.z + hv.w*b.w;
                    a = wi1[k]; b = wh1[k];
                    acc1 += ev.x*a.x + ev.y*a.y + ev.z*a.z + ev.w*a.w
                          + hv.x*b.x + hv.y*b.y + hv.z*b.z + hv.w*b.w;
                    a = wi2[k]; b = wh2[k];
                    acc2 += ev.x*a.x + ev.y*a.y + ev.z*a.z + ev.w*a.w
                          + hv.x*b.x + hv.y*b.y + hv.z*b.z + hv.w*b.w;
                    a = wi3[k]; b = wh3[k];
                    acc3 += ev.x*a.x + ev.y*a.y + ev.z*a.z + ev.w*a.w
                          + hv.x*b.x + hv.y*b.y + hv.z*b.z + hv.w*b.w;
                }
            }
            acc0 = wreduce(acc0); acc1 = wreduce(acc1);
            acc2 = wreduce(acc2); acc3 = wreduce(acc3);

            const float gi = acc0 + b_ih[0 * H + n] + b_hh[0 * H + n];
            const float gf = acc1 + b_ih[1 * H + n] + b_hh[1 * H + n];
            const float gg = acc2 + b_ih[2 * H + n] + b_hh[2 * H + n];
            const float go = acc3 + b_ih[3 * H + n] + b_hh[3 * H + n];

            const float cprev = (t == 0) ? cloc0 : cloc1;
            const float c2 = sigf(gf) * cprev + sigf(gi) * tanhf(gg);
            const float h2 = sigf(go) * tanhf(c2);
            if (t == 0) cloc0 = c2; else cloc1 = c2;
            if (lane == 0) g_hbuf[wbuf][n] = h2;
        }

        __threadfence();
        grid_sync();   // all h2 visible chip-wide

        // ---- decode + argmax (redundant per CTA; deterministic) ----
        const float* dec; int ncls;
        if (cell == 0) { dec = dec_act; ncls = 4; }
        else {
            const int bid = (cell + 1) >> 1;
            if (cell & 1) { dec = dec_block + (size_t)(bid - 1) * (NBK - 1) * H; ncls = bid; }
            else          { dec = dec_act   + (size_t)bid * 4 * H;               ncls = 4;   }
        }
        if (wid == 0) {
            const float4* hp = (const float4*)g_hbuf[wbuf];
            float best = 0.f; int bi = 0;
            for (int j = 0; j < ncls; j++) {
                const float4* dr = (const float4*)(dec + (size_t)j * H);
                float s = 0.f;
                for (int k = lane; k < H / 4; k += 32) {
                    const float4 d = dr[k]; const float4 hv = hp[k];
                    s += d.x*hv.x + d.y*hv.y + d.z*hv.z + d.w*hv.w;
                }
                s = wreduce(s);
                if (j == 0 || s > best) { best = s; bi = j; }   // first-max-wins (jnp.argmax)
            }
            if (lane == 0) idx_sm = bi;
        }
        __syncthreads();
        idx = idx_sm;
    }

    // ---- publish c, then replicate outputs to all 1024 rows ----
    if (lane == 0) {
        g_cbuf[gw]        = cloc0;
        g_cbuf[gw + TOTW] = cloc1;
    }
    __threadfence();
    grid_sync();

    const float* hfin = g_hbuf[(2 * NBK - 2) & 1];  // last cell (22) wrote buffer 0
    for (int i = tid; i < H; i += NTHR) { h_sm[i] = hfin[i]; e_sm[i] = g_cbuf[i]; }
    __syncthreads();

    if (cta == 0) {
        const float idxf = (float)idx;
        for (int i = tid; i < BSZ; i += NTHR) out[i] = idxf;
    }
    float4* outh = (float4*)(out + BSZ);
    float4* outc = (float4*)(out + BSZ + (size_t)BSZ * H);
    for (int r = cta; r < BSZ; r += NCTA) {
        const size_t ro = (size_t)r * (H / 4);
        for (int i = tid; i < H / 4; i += NTHR) {
            outh[ro + i] = ((float4*)h_sm)[i];
            outc[ro + i] = ((float4*)e_sm)[i];
        }
    }
}

extern "C" void kernel_launch(void* const* d_in, const int* in_sizes, int n_in,
                              void* d_out, int out_size) {
    // metadata order: inputs, W_ih, W_hh, b_ih, b_hh, enc_act, enc_block, dec_act, dec_block
    const float* W_ih      = (const float*)d_in[1];
    const float* W_hh      = (const float*)d_in[2];
    const float* b_ih      = (const float*)d_in[3];
    const float* b_hh      = (const float*)d_in[4];
    const float* enc_act   = (const float*)d_in[5];
    const float* enc_block = (const float*)d_in[6];
    const float* dec_act   = (const float*)d_in[7];
    const float* dec_block = (const float*)d_in[8];
    float* out = (float*)d_out;

    controller_lstm_kernel<<<NCTA, NTHR>>>(W_ih, W_hh, b_ih, b_hh,
                                           enc_act, enc_block, dec_act, dec_block,
                                           out);
}

// round 2
// speedup vs baseline: 2.4177x; 2.4177x over previous
#include <cuda_runtime.h>
#include <math.h>

// ---------------------------------------------------------------------------
// ControllerLSTM on GB300, round 2.
// Round-1 insight kept: all 1024 batch rows identical -> compute B=1.
// New: the LSTM input embedding comes from a finite set of 110 rows, so
// precompute T[r][m] = e_r @ W_ih^T + b_ih + b_hh ONCE (kernel 1, a small
// fp32 GEMM). The persistent main kernel (kernel 2) then streams only W_hh
// (64 MB/cell) which is L2-resident, plus 4 scalar table reads per warp.
// ---------------------------------------------------------------------------

#define H    2048
#define H4   (H/4)
#define BSZ  1024
#define NBK  12
#define M4H  8192

// ---- main kernel config ----
#define NCTA    128
#define NTHR    512
#define NWARP_M (NTHR/32)          // 16 warps
#define TOTW    (NCTA*NWARP_M)     // 2048 warps == H gate columns

// ---- precompute (table) config ----
#define PC_ROWS     112            // 44 act + 66 block + 1 bias-only + 1 pad
#define PC_USED     110
#define PC_BIAS_ROW 110
#define PC_THREADS  256
#define PC_KC       32
#define PC_ST       36             // smem row stride (floats), 16B-aligned

__device__ float    g_table[PC_ROWS * M4H];   // 3.7 MB
__device__ float    g_hbuf[2][H];
__device__ float    g_cbuf[H];
__device__ unsigned g_bar_count = 0;
__device__ unsigned g_bar_gen   = 0;

__device__ __forceinline__ void grid_sync() {
    __syncthreads();
    if (threadIdx.x == 0) {
        __threadfence();
        unsigned gen = *((volatile unsigned*)&g_bar_gen);
        if (atomicAdd(&g_bar_count, 1u) == NCTA - 1) {
            *((volatile unsigned*)&g_bar_count) = 0;
            __threadfence();
            atomicAdd(&g_bar_gen, 1u);
        } else {
            while (*((volatile unsigned*)&g_bar_gen) == gen) { __nanosleep(40); }
        }
    }
    __syncthreads();
}

__device__ __forceinline__ float wred(float v) {
    #pragma unroll
    for (int o = 16; o > 0; o >>= 1) v += __shfl_xor_sync(0xffffffffu, v, o);
    return v;
}

__device__ __forceinline__ float sigf(float x) { return 1.0f / (1.0f + expf(-x)); }

// ===========================================================================
// Kernel 1: table precompute.  T[r][m] = e_r . W_ih[m,:] + b_ih[m] + b_hh[m]
// GEMM: M=8192 (gate rows), N=112 (embedding rows), K=2048.
// CTA tile 64m x 112r, thread tile 4m x 7r, K-chunks of 32 with reg prefetch.
// Warp layout: (tid&15)->r (16 distinct, low smem conflict), (tid>>4)->m.
// ===========================================================================
__global__ __launch_bounds__(PC_THREADS, 1)
void precompute_gates_ih(const float* __restrict__ W_ih,
                         const float* __restrict__ b_ih,
                         const float* __restrict__ b_hh,
                         const float* __restrict__ enc_act,
                         const float* __restrict__ enc_block)
{
    __shared__ float Wsm[64][PC_ST];
    __shared__ float Esm[PC_ROWS][PC_ST];
    __shared__ const float* srcp[PC_ROWS];

    const int tid = threadIdx.x;

    // embedding-row source pointers (110 real rows; 110 = bias-only, 111 pad)
    for (int r = tid; r < PC_ROWS; r += PC_THREADS) {
        const float* p = 0;
        if (r < 44) {
            p = enc_act + (size_t)r * H;                       // (bid-1)*4 + idx
        } else if (r < PC_USED) {
            int r2 = r - 44;                                   // triangular block region
            int bid = 1;
            while (bid * (bid + 1) / 2 <= r2) bid++;
            int j = r2 - bid * (bid - 1) / 2;
            p = enc_block + (size_t)((bid - 1) * (NBK - 1) + j) * H;
        }
        srcp[r] = p;                                           // null -> zeros
    }
    __syncthreads();

    const int m0 = blockIdx.x * 64;
    const int tm = (tid >> 4) * 4;      // 0..60
    const int tr = (tid & 15) * 7;      // 0..105

    float acc[7][4];
    #pragma unroll
    for (int j = 0; j < 7; j++)
        #pragma unroll
        for (int i = 0; i < 4; i++) acc[j][i] = 0.f;

    // preload chunk 0 into smem
    for (int i = tid; i < 512; i += PC_THREADS) {
        int row = i >> 3, c = i & 7;
        *(float4*)&Wsm[row][c * 4] = *(const float4*)&W_ih[(size_t)(m0 + row) * H + c * 4];
    }
    for (int i = tid; i < 896; i += PC_THREADS) {
        int row = i >> 3, c = i & 7;
        const float* p = srcp[row];
        float4 v = make_float4(0.f, 0.f, 0.f, 0.f);
        if (p) v = *(const float4*)&p[c * 4];
        *(float4*)&Esm[row][c * 4] = v;
    }
    __syncthreads();

    for (int chunk = 0; chunk < H / PC_KC; chunk++) {
        // register-prefetch next chunk (LDG issued before compute)
        float4 wpre[2], epre[4];
        const bool more = (chunk + 1 < H / PC_KC);
        if (more) {
            const int kcn = (chunk + 1) * PC_KC;
            #pragma unroll
            for (int t = 0; t < 2; t++) {
                int i = tid + t * PC_THREADS; int row = i >> 3, c = i & 7;
                wpre[t] = *(const float4*)&W_ih[(size_t)(m0 + row) * H + kcn + c * 4];
            }
            #pragma unroll
            for (int t = 0; t < 4; t++) {
                int i = tid + t * PC_THREADS;
                epre[t] = make_float4(0.f, 0.f, 0.f, 0.f);
                if (i < 896) {
                    int row = i >> 3, c = i & 7;
                    const float* p = srcp[row];
                    if (p) epre[t] = *(const float4*)&p[kcn + c * 4];
                }
            }
        }
        // compute current chunk from smem
        #pragma unroll
        for (int kk = 0; kk < PC_KC; kk += 4) {
            float4 w[4], e[7];
            #pragma unroll
            for (int i = 0; i < 4; i++) w[i] = *(const float4*)&Wsm[tm + i][kk];
            #pragma unroll
            for (int j = 0; j < 7; j++) e[j] = *(const float4*)&Esm[tr + j][kk];
            #pragma unroll
            for (int j = 0; j < 7; j++)
                #pragma unroll
                for (int i = 0; i < 4; i++)
                    acc[j][i] += w[i].x * e[j].x + w[i].y * e[j].y
                               + w[i].z * e[j].z + w[i].w * e[j].w;
        }
        if (more) {
            __syncthreads();   // everyone done reading smem
            #pragma unroll
            for (int t = 0; t < 2; t++) {
                int i = tid + t * PC_THREADS; int row = i >> 3, c = i & 7;
                *(float4*)&Wsm[row][c * 4] = wpre[t];
            }
            #pragma unroll
            for (int t = 0; t < 4; t++) {
                int i = tid + t * PC_THREADS;
                if (i < 896) { int row = i >> 3, c = i & 7; *(float4*)&Esm[row][c * 4] = epre[t]; }
            }
            __syncthreads();   // smem ready
        }
    }

    // epilogue: fold biases, write table
    float bsum[4];
    #pragma unroll
    for (int i = 0; i < 4; i++) { int m = m0 + tm + i; bsum[i] = b_ih[m] + b_hh[m]; }
    #pragma unroll
    for (int j = 0; j < 7; j++) {
        float4 v;
        v.x = acc[j][0] + bsum[0]; v.y = acc[j][1] + bsum[1];
        v.z = acc[j][2] + bsum[2]; v.w = acc[j][3] + bsum[3];
        *(float4*)&g_table[(size_t)(tr + j) * M4H + m0 + tm] = v;
    }
}

// ===========================================================================
// Kernel 2: persistent controller. 2048 warps, warp owns gate column n=gw.
// Per cell: GEMV h.W_hh (4 streams of 8KB, L2-resident) + table row scalars,
// LSTM pointwise, grid barrier, stage h, distributed decode + local argmax.
// ===========================================================================
__global__ __launch_bounds__(NTHR, 1)
void controller_main(const float* __restrict__ W_hh,
                     const float* __restrict__ dec_act,
                     const float* __restrict__ dec_block,
                     float* __restrict__ out)
{
    __shared__ float h_sm[H];
    __shared__ float c_sm[H];
    __shared__ float dec_sm[NBK - 1];

    const int tid  = threadIdx.x;
    const int lane = tid & 31;
    const int wid  = tid >> 5;
    const int gw   = blockIdx.x * NWARP_M + wid;   // gate column n in [0,2048)

    float cloc = 0.f;
    int   idx  = 0;

    for (int cell = 0; cell < 2 * NBK - 1; cell++) {
        const int wbuf = cell & 1;

        // table row for this cell's input embedding
        int row;
        if (cell == 0) row = PC_BIAS_ROW;
        else {
            const int bid = (cell + 1) >> 1;
            if (cell & 1) row = (bid - 1) * 4 + idx;               // enc_act
            else          row = 44 + bid * (bid - 1) / 2 + idx;    // enc_block (valid j<bid)
        }

        // GEMV over W_hh (h_sm staged at end of previous cell)
        float4 acc = make_float4(0.f, 0.f, 0.f, 0.f);
        if (cell > 0) {
            const float4* w0 = (const float4*)(W_hh + ((size_t)0 * H + gw) * H);
            const float4* w1 = (const float4*)(W_hh + ((size_t)1 * H + gw) * H);
            const float4* w2 = (const float4*)(W_hh + ((size_t)2 * H + gw) * H);
            const float4* w3 = (const float4*)(W_hh + ((size_t)3 * H + gw) * H);
            const float4* hp = (const float4*)h_sm;
            #pragma unroll 4
            for (int j = lane; j < H4; j += 32) {
                const float4 hv = hp[j];
                const float4 a0 = w0[j], a1 = w1[j], a2 = w2[j], a3 = w3[j];
                acc.x += a0.x*hv.x + a0.y*hv.y + a0.z*hv.z + a0.w*hv.w;
                acc.y += a1.x*hv.x + a1.y*hv.y + a1.z*hv.z + a1.w*hv.w;
                acc.z += a2.x*hv.x + a2.y*hv.y + a2.z*hv.z + a2.w*hv.w;
                acc.w += a3.x*hv.x + a3.y*hv.y + a3.z*hv.z + a3.w*hv.w;
            }
        }
        acc.x = wred(acc.x); acc.y = wred(acc.y);
        acc.z = wred(acc.z); acc.w = wred(acc.w);

        const float* trow = g_table + (size_t)row * M4H;
        const float gi = acc.x + trow[0 * H + gw];
        const float gf = acc.y + trow[1 * H + gw];
        const float gg = acc.z + trow[2 * H + gw];
        const float go = acc.w + trow[3 * H + gw];

        const float c2 = sigf(gf) * cloc + sigf(gi) * tanhf(gg);
        const float h2 = sigf(go) * tanhf(c2);
        cloc = c2;
        if (lane == 0) {
            g_hbuf[wbuf][gw] = h2;
            if (cell == 2 * NBK - 2) g_cbuf[gw] = c2;
        }
        __threadfence();
        grid_sync();

        // stage new h into smem (L1-bypassing loads; other SMs wrote it)
        ((float4*)h_sm)[tid] = __ldcv((const float4*)g_hbuf[wbuf] + tid);  // NTHR==H4
        __syncthreads();

        // distributed decode: warp j computes class j's logit
        const float* dec; int ncls;
        if (cell == 0) { dec = dec_act; ncls = 4; }
        else {
            const int bid = (cell + 1) >> 1;
            if (cell & 1) { dec = dec_block + (size_t)(bid - 1) * (NBK - 1) * H; ncls = bid; }
            else          { dec = dec_act   + (size_t)bid * 4 * H;               ncls = 4;   }
        }
        if (wid < ncls) {
            const float4* dr = (const float4*)(dec + (size_t)wid * H);
            const float4* hp = (const float4*)h_sm;
            float s = 0.f;
            #pragma unroll 4
            for (int j = lane; j < H4; j += 32) {
                const float4 d = dr[j], hv = hp[j];
                s += d.x*hv.x + d.y*hv.y + d.z*hv.z + d.w*hv.w;
            }
            s = wred(s);
            if (lane == 0) dec_sm[wid] = s;
        }
        __syncthreads();
        // first-max-wins argmax, computed redundantly by every thread
        float best = dec_sm[0]; int bi = 0;
        for (int j = 1; j < ncls; j++) { float v = dec_sm[j]; if (v > best) { best = v; bi = j; } }
        idx = bi;
    }

    // stage final c; h_sm already holds final h
    ((float4*)c_sm)[tid] = __ldcv((const float4*)g_cbuf + tid);
    __syncthreads();

    // replicate outputs to all 1024 (identical) batch rows
    if (blockIdx.x == 0) {
        const float idxf = (float)idx;
        for (int i = tid; i < BSZ; i += NTHR) out[i] = idxf;
    }
    float4* outh = (float4*)(out + BSZ);
    float4* outc = (float4*)(out + BSZ + (size_t)BSZ * H);
    for (int r = blockIdx.x; r < BSZ; r += NCTA) {
        const size_t ro = (size_t)r * H4;
        for (int i = tid; i < H4; i += NTHR) {
            outh[ro + i] = ((const float4*)h_sm)[i];
            outc[ro + i] = ((const float4*)c_sm)[i];
        }
    }
}

extern "C" void kernel_launch(void* const* d_in, const int* in_sizes, int n_in,
                              void* d_out, int out_size) {
    // metadata order: inputs, W_ih, W_hh, b_ih, b_hh, enc_act, enc_block, dec_act, dec_block
    const float* W_ih      = (const float*)d_in[1];
    const float* W_hh      = (const float*)d_in[2];
    const float* b_ih      = (const float*)d_in[3];
    const float* b_hh      = (const float*)d_in[4];
    const float* enc_act   = (const float*)d_in[5];
    const float* enc_block = (const float*)d_in[6];
    const float* dec_act   = (const float*)d_in[7];
    const float* dec_block = (const float*)d_in[8];
    float* out = (float*)d_out;

    precompute_gates_ih<<<128, PC_THREADS>>>(W_ih, b_ih, b_hh, enc_act, enc_block);
    controller_main<<<NCTA, NTHR>>>(W_hh, dec_act, dec_block, out);
}

// round 4
// speedup vs baseline: 2.6644x; 1.1020x over previous
#include <cuda_runtime.h>
#include <cuda_fp16.h>
#include <math.h>

// ---------------------------------------------------------------------------
// ControllerLSTM on GB300, round 3.
// Kept: batch collapse (B=1), W_ih folded into a 110-row precomputed gate
// table, persistent main kernel.
// New: (1) W_hh compressed to fp16 once -> halves L2 traffic in the 22 GEMVs,
//      (2) flag-array grid barrier (parallel arrives) instead of one atomic
//          counter (serialized),
//      (3) precompute GEMM K-split 2 -> 256 CTAs cover all 148 SMs; main
//          kernel sums the two table halves (4 extra scalar loads per warp).
// ---------------------------------------------------------------------------

#define H    2048
#define H4   (H/4)
#define H8   (H/8)
#define BSZ  1024
#define NBK  12
#define M4H  8192

// ---- main kernel config ----
#define NCTA    128
#define NTHR    512
#define NWARP_M (NTHR/32)          // 16 warps -> 2048 warps == H gate columns

// ---- precompute (table) config ----
#define PC_ROWS     112            // 44 act + 66 block + 1 bias-only + 1 pad
#define PC_USED     110
#define PC_BIAS_ROW 110
#define PC_THREADS  256
#define PC_KC       32
#define PC_ST       36             // smem row stride (floats)
#define KSPLIT      2
#define KHALF       (H / KSPLIT)   // 1024

__device__ float    g_table[KSPLIT * PC_ROWS * M4H];  // 7.3 MB
__device__ __half   g_whh[(size_t)4 * H * H];          // 33.5 MB fp16 W_hh
__device__ float    g_hbuf[2][H];
__device__ float    g_cbuf[H];

// flag barrier state (monotonic generations; no reset needed)
#define FLAG_STRIDE 8
__device__ volatile unsigned g_arrive[NCTA * FLAG_STRIDE];
__device__ volatile unsigned g_release;

__device__ __forceinline__ void grid_sync_flags(unsigned gen) {
    __syncthreads();
    const int tid = threadIdx.x;
    if (blockIdx.x == 0) {
        if (tid == 0) { __threadfence(); g_arrive[0] = gen; }
        if (tid < NCTA) {
            while (g_arrive[tid * FLAG_STRIDE] != gen) { }
        }
        __syncthreads();
        if (tid == 0) { __threadfence(); g_release = gen; }
    } else {
        if (tid == 0) {
            __threadfence();
            g_arrive[blockIdx.x * FLAG_STRIDE] = gen;
            while (g_release != gen) { }
        }
    }
    __syncthreads();
}

__device__ __forceinline__ float wred(float v) {
    #pragma unroll
    for (int o = 16; o > 0; o >>= 1) v += __shfl_xor_sync(0xffffffffu, v, o);
    return v;
}

__device__ __forceinline__ float sigf(float x) { return 1.0f / (1.0f + expf(-x)); }

// 8-element fp16 dot with fp32 h / fp32 accumulate
__device__ __forceinline__ float dot8(uint4 w, float4 ha, float4 hb) {
    union { unsigned u; __half2 h; } c0, c1, c2, c3;
    c0.u = w.x; c1.u = w.y; c2.u = w.z; c3.u = w.w;
    const float2 f0 = __half22float2(c0.h);
    const float2 f1 = __half22float2(c1.h);
    const float2 f2 = __half22float2(c2.h);
    const float2 f3 = __half22float2(c3.h);
    return f0.x*ha.x + f0.y*ha.y + f1.x*ha.z + f1.y*ha.w
         + f2.x*hb.x + f2.y*hb.y + f3.x*hb.z + f3.y*hb.w;
}

// ===========================================================================
// Kernel 0: convert W_hh (fp32) -> g_whh (fp16), same [4H][H] layout.
// ===========================================================================
__global__ __launch_bounds__(256, 2)
void convert_whh(const float* __restrict__ W_hh)
{
    const size_t n4 = (size_t)4 * H * H / 4;   // float4 count
    const size_t stride = (size_t)gridDim.x * blockDim.x;
    uint2* __restrict__ dst = (uint2*)g_whh;
    const float4* __restrict__ src = (const float4*)W_hh;
    for (size_t k = blockIdx.x * blockDim.x + threadIdx.x; k < n4; k += stride) {
        const float4 v = src[k];
        union { __half2 h; unsigned u; } a, b;
        a.h = __floats2half2_rn(v.x, v.y);
        b.h = __floats2half2_rn(v.z, v.w);
        dst[k] = make_uint2(a.u, b.u);
    }
}

// ===========================================================================
// Kernel 1: table precompute, K-split across blockIdx.y.
//   T[ky][r][m] = e_r[kbase:kbase+1024] . W_ih[m, kbase:kbase+1024]
//   (+ b_ih[m] + b_hh[m] folded into ky==0 half)
// CTA tile 64m x 112r, thread tile 4m x 7r, K-chunks of 32 w/ reg prefetch.
// ===========================================================================
__global__ __launch_bounds__(PC_THREADS, 1)
void precompute_gates_ih(const float* __restrict__ W_ih,
                         const float* __restrict__ b_ih,
                         const float* __restrict__ b_hh,
                         const float* __restrict__ enc_act,
                         const float* __restrict__ enc_block)
{
    __shared__ float Wsm[64][PC_ST];
    __shared__ float Esm[PC_ROWS][PC_ST];
    __shared__ const float* srcp[PC_ROWS];

    const int tid   = threadIdx.x;
    const int ky    = blockIdx.y;
    const int kbase = ky * KHALF;

    for (int r = tid; r < PC_ROWS; r += PC_THREADS) {
        const float* p = 0;
        if (r < 44) {
            p = enc_act + (size_t)r * H;
        } else if (r < PC_USED) {
            int r2 = r - 44;
            int bid = 1;
            while (bid * (bid + 1) / 2 <= r2) bid++;
            int j = r2 - bid * (bid - 1) / 2;
            p = enc_block + (size_t)((bid - 1) * (NBK - 1) + j) * H;
        }
        srcp[r] = p;
    }
    __syncthreads();

    const int m0 = blockIdx.x * 64;
    const int tm = (tid >> 4) * 4;
    const int tr = (tid & 15) * 7;

    float acc[7][4];
    #pragma unroll
    for (int j = 0; j < 7; j++)
        #pragma unroll
        for (int i = 0; i < 4; i++) acc[j][i] = 0.f;

    // preload chunk 0
    for (int i = tid; i < 512; i += PC_THREADS) {
        int row = i >> 3, c = i & 7;
        *(float4*)&Wsm[row][c * 4] =
            *(const float4*)&W_ih[(size_t)(m0 + row) * H + kbase + c * 4];
    }
    for (int i = tid; i < 896; i += PC_THREADS) {
        int row = i >> 3, c = i & 7;
        const float* p = srcp[row];
        float4 v = make_float4(0.f, 0.f, 0.f, 0.f);
        if (p) v = *(const float4*)&p[kbase + c * 4];
        *(float4*)&Esm[row][c * 4] = v;
    }
    __syncthreads();

    const int nchunk = KHALF / PC_KC;   // 32
    for (int chunk = 0; chunk < nchunk; chunk++) {
        float4 wpre[2], epre[4];
        const bool more = (chunk + 1 < nchunk);
        if (more) {
            const int kcn = kbase + (chunk + 1) * PC_KC;
            #pragma unroll
            for (int t = 0; t < 2; t++) {
                int i = tid + t * PC_THREADS; int row = i >> 3, c = i & 7;
                wpre[t] = *(const float4*)&W_ih[(size_t)(m0 + row) * H + kcn + c * 4];
            }
            #pragma unroll
            for (int t = 0; t < 4; t++) {
                int i = tid + t * PC_THREADS;
                epre[t] = make_float4(0.f, 0.f, 0.f, 0.f);
                if (i < 896) {
                    int row = i >> 3, c = i & 7;
                    const float* p = srcp[row];
                    if (p) epre[t] = *(const float4*)&p[kcn + c * 4];
                }
            }
        }
        #pragma unroll
        for (int kk = 0; kk < PC_KC; kk += 4) {
            float4 w[4], e[7];
            #pragma unroll
            for (int i = 0; i < 4; i++) w[i] = *(const float4*)&Wsm[tm + i][kk];
            #pragma unroll
            for (int j = 0; j < 7; j++) e[j] = *(const float4*)&Esm[tr + j][kk];
            #pragma unroll
            for (int j = 0; j < 7; j++)
                #pragma unroll
                for (int i = 0; i < 4; i++)
                    acc[j][i] += w[i].x * e[j].x + w[i].y * e[j].y
                               + w[i].z * e[j].z + w[i].w * e[j].w;
        }
        if (more) {
            __syncthreads();
            #pragma unroll
            for (int t = 0; t < 2; t++) {
                int i = tid + t * PC_THREADS; int row = i >> 3, c = i & 7;
                *(float4*)&Wsm[row][c * 4] = wpre[t];
            }
            #pragma unroll
            for (int t = 0; t < 4; t++) {
                int i = tid + t * PC_THREADS;
                if (i < 896) { int row = i >> 3, c = i & 7; *(float4*)&Esm[row][c * 4] = epre[t]; }
            }
            __syncthreads();
        }
    }

    float bsum[4] = {0.f, 0.f, 0.f, 0.f};
    if (ky == 0) {
        #pragma unroll
        for (int i = 0; i < 4; i++) { int m = m0 + tm + i; bsum[i] = b_ih[m] + b_hh[m]; }
    }
    float* tout = g_table + (size_t)ky * PC_ROWS * M4H;
    #pragma unroll
    for (int j = 0; j < 7; j++) {
        float4 v;
        v.x = acc[j][0] + bsum[0]; v.y = acc[j][1] + bsum[1];
        v.z = acc[j][2] + bsum[2]; v.w = acc[j][3] + bsum[3];
        *(float4*)&tout[(size_t)(tr + j) * M4H + m0 + tm] = v;
    }
}

// ===========================================================================
// Kernel 2: persistent controller. 2048 warps, warp owns gate column n=gw.
// ===========================================================================
__global__ __launch_bounds__(NTHR, 1)
void controller_main(const float* __restrict__ dec_act,
                     const float* __restrict__ dec_block,
                     float* __restrict__ out)
{
    __shared__ float h_sm[H];
    __shared__ float c_sm[H];
    __shared__ float dec_sm[NBK - 1];

    const int tid  = threadIdx.x;
    const int lane = tid & 31;
    const int wid  = tid >> 5;
    const int gw   = blockIdx.x * NWARP_M + wid;

    float cloc = 0.f;
    int   idx  = 0;
    unsigned gen = 0;

    const __half* wb = g_whh;

    for (int cell = 0; cell < 2 * NBK - 1; cell++) {
        const int wbuf = cell & 1;

        int row;
        if (cell == 0) row = PC_BIAS_ROW;
        else {
            const int bid = (cell + 1) >> 1;
            if (cell & 1) row = (bid - 1) * 4 + idx;
            else          row = 44 + bid * (bid - 1) / 2 + idx;
        }

        // GEMV over fp16 W_hh (h_sm staged at end of previous cell)
        float4 acc = make_float4(0.f, 0.f, 0.f, 0.f);
        if (cell > 0) {
            const uint4* w0 = (const uint4*)(wb + ((size_t)0 * H + gw) * H);
            const uint4* w1 = (const uint4*)(wb + ((size_t)1 * H + gw) * H);
            const uint4* w2 = (const uint4*)(wb + ((size_t)2 * H + gw) * H);
            const uint4* w3 = (const uint4*)(wb + ((size_t)3 * H + gw) * H);
            const float4* hp = (const float4*)h_sm;
            #pragma unroll 2
            for (int j = lane; j < H8; j += 32) {
                const float4 ha = hp[2 * j], hbv = hp[2 * j + 1];
                const uint4 a0 = w0[j], a1 = w1[j], a2 = w2[j], a3 = w3[j];
                acc.x += dot8(a0, ha, hbv);
                acc.y += dot8(a1, ha, hbv);
                acc.z += dot8(a2, ha, hbv);
                acc.w += dot8(a3, ha, hbv);
            }
        }
        acc.x = wred(acc.x); acc.y = wred(acc.y);
        acc.z = wred(acc.z); acc.w = wred(acc.w);

        const float* t0 = g_table + (size_t)row * M4H;
        const float* t1 = t0 + (size_t)PC_ROWS * M4H;
        const float gi = acc.x + t0[0 * H + gw] + t1[0 * H + gw];
        const float gf = acc.y + t0[1 * H + gw] + t1[1 * H + gw];
        const float gg = acc.z + t0[2 * H + gw] + t1[2 * H + gw];
        const float go = acc.w + t0[3 * H + gw] + t1[3 * H + gw];

        const float c2 = sigf(gf) * cloc + sigf(gi) * tanhf(gg);
        const float h2 = sigf(go) * tanhf(c2);
        cloc = c2;
        if (lane == 0) {
            g_hbuf[wbuf][gw] = h2;
            if (cell == 2 * NBK - 2) g_cbuf[gw] = c2;
        }
        gen++;
        grid_sync_flags(gen);

        // stage new h into smem (L1-bypassing; other SMs wrote it)
        ((float4*)h_sm)[tid] = __ldcv((const float4*)g_hbuf[wbuf] + tid);  // NTHR==H4
        __syncthreads();

        // distributed decode: warp j computes class j's logit
        const float* dec; int ncls;
        if (cell == 0) { dec = dec_act; ncls = 4; }
        else {
            const int bid = (cell + 1) >> 1;
            if (cell & 1) { dec = dec_block + (size_t)(bid - 1) * (NBK - 1) * H; ncls = bid; }
            else          { dec = dec_act   + (size_t)bid * 4 * H;               ncls = 4;   }
        }
        if (wid < ncls) {
            const float4* dr = (const float4*)(dec + (size_t)wid * H);
            const float4* hp = (const float4*)h_sm;
            float s = 0.f;
            #pragma unroll 4
            for (int j = lane; j < H4; j += 32) {
                const float4 d = dr[j], hv = hp[j];
                s += d.x*hv.x + d.y*hv.y + d.z*hv.z + d.w*hv.w;
            }
            s = wred(s);
            if (lane == 0) dec_sm[wid] = s;
        }
        __syncthreads();
        float best = dec_sm[0]; int bi = 0;
        for (int j = 1; j < ncls; j++) { float v = dec_sm[j]; if (v > best) { best = v; bi = j; } }
        idx = bi;
    }

    // stage final c; h_sm already holds final h
    ((float4*)c_sm)[tid] = __ldcv((const float4*)g_cbuf + tid);
    __syncthreads();

    // replicate outputs to all 1024 (identical) batch rows
    if (blockIdx.x == 0) {
        const float idxf = (float)idx;
        for (int i = tid; i < BSZ; i += NTHR) out[i] = idxf;
    }
    float4* outh = (float4*)(out + BSZ);
    float4* outc = (float4*)(out + BSZ + (size_t)BSZ * H);
    for (int r = blockIdx.x; r < BSZ; r += NCTA) {
        const size_t ro = (size_t)r * H4;
        for (int i = tid; i < H4; i += NTHR) {
            outh[ro + i] = ((const float4*)h_sm)[i];
            outc[ro + i] = ((const float4*)c_sm)[i];
        }
    }
}

extern "C" void kernel_launch(void* const* d_in, const int* in_sizes, int n_in,
                              void* d_out, int out_size) {
    // metadata order: inputs, W_ih, W_hh, b_ih, b_hh, enc_act, enc_block, dec_act, dec_block
    const float* W_ih      = (const float*)d_in[1];
    const float* W_hh      = (const float*)d_in[2];
    const float* b_ih      = (const float*)d_in[3];
    const float* b_hh      = (const float*)d_in[4];
    const float* enc_act   = (const float*)d_in[5];
    const float* enc_block = (const float*)d_in[6];
    const float* dec_act   = (const float*)d_in[7];
    const float* dec_block = (const float*)d_in[8];
    float* out = (float*)d_out;

    convert_whh<<<512, 256>>>(W_hh);
    dim3 pcg(128, KSPLIT);
    precompute_gates_ih<<<pcg, PC_THREADS>>>(W_ih, b_ih, b_hh, enc_act, enc_block);
    controller_main<<<NCTA, NTHR>>>(dec_act, dec_block, out);
}

// round 5
// speedup vs baseline: 2.8326x; 1.0631x over previous
#include <cuda_runtime.h>
#include <cuda_fp16.h>
#include <math.h>

// ---------------------------------------------------------------------------
// ControllerLSTM on GB300, round 4.
// Kept: batch collapse (B=1), fp16 weights, persistent main kernel, flag
// barrier. New: NO precompute GEMM (it was fp32-FMA-pipe bound at ~128 us and
// computed 110 table rows of which only 22 are used). Instead both W_ih and
// W_hh are converted once into a fused fp16 layout g_wc[g][n][0:2048]=ih,
// [2048:4096]=hh, and each cell's gates are one fused GEMV against the
// smem vector [e | h] (e kept fp32 -> negligible added rounding error).
// 67 MB of fp16 weights are L2-resident; per-cell traffic = 64 MB from L2.
// ---------------------------------------------------------------------------

#define H    2048
#define H2X  (2*H)        // 4096 fused k-length
#define H4   (H/4)
#define BSZ  1024
#define NBK  12

#define NCTA    128
#define NTHR    512
#define NWARP_M (NTHR/32)          // 16 warps/CTA -> 2048 warps == H columns

__device__ __half g_wc[(size_t)4 * H * H2X];   // 67.1 MB fused fp16 weights
__device__ float  g_hbuf[2][H];
__device__ float  g_cbuf[H];

// flag barrier (monotonic generations, parallel arrives)
#define FLAG_STRIDE 8
__device__ volatile unsigned g_arrive[NCTA * FLAG_STRIDE];
__device__ volatile unsigned g_release;

__device__ __forceinline__ void grid_sync_flags(unsigned gen) {
    __syncthreads();
    const int tid = threadIdx.x;
    if (blockIdx.x == 0) {
        if (tid == 0) { __threadfence(); g_arrive[0] = gen; }
        if (tid < NCTA) {
            while (g_arrive[tid * FLAG_STRIDE] != gen) { }
        }
        __syncthreads();
        if (tid == 0) { __threadfence(); g_release = gen; }
    } else {
        if (tid == 0) {
            __threadfence();
            g_arrive[blockIdx.x * FLAG_STRIDE] = gen;
            while (g_release != gen) { }
        }
    }
    __syncthreads();
}

__device__ __forceinline__ float wred(float v) {
    #pragma unroll
    for (int o = 16; o > 0; o >>= 1) v += __shfl_xor_sync(0xffffffffu, v, o);
    return v;
}

__device__ __forceinline__ float sigf(float x) { return 1.0f / (1.0f + expf(-x)); }

// 8-halves dot against 8 fp32 values, fp32 accumulate
__device__ __forceinline__ float dot8(uint4 w, float4 xa, float4 xb) {
    union { unsigned u; __half2 h; } c0, c1, c2, c3;
    c0.u = w.x; c1.u = w.y; c2.u = w.z; c3.u = w.w;
    const float2 f0 = __half22float2(c0.h);
    const float2 f1 = __half22float2(c1.h);
    const float2 f2 = __half22float2(c2.h);
    const float2 f3 = __half22float2(c3.h);
    return f0.x*xa.x + f0.y*xa.y + f1.x*xa.z + f1.y*xa.w
         + f2.x*xb.x + f2.y*xb.y + f3.x*xb.z + f3.y*xb.w;
}

// ===========================================================================
// Kernel 0: fused conversion. g_wc[(g*H+n)*4096 + k]:
//   k <  2048 : fp16( W_ih[(g*H+n)*2048 + k] )
//   k >= 2048 : fp16( W_hh[(g*H+n)*2048 + k-2048] )
// ===========================================================================
__global__ __launch_bounds__(256, 2)
void convert_weights(const float* __restrict__ W_ih, const float* __restrict__ W_hh)
{
    const size_t n2 = (size_t)4 * H * H2X / 4;   // uint2 (4-half) chunks
    const size_t stride = (size_t)gridDim.x * blockDim.x;
    uint2* __restrict__ dst = (uint2*)g_wc;
    for (size_t i = blockIdx.x * blockDim.x + threadIdx.x; i < n2; i += stride) {
        const size_t o   = i * 4;          // half index
        const size_t row = o >> 12;        // /4096 : row = g*H + n
        const size_t k0  = o & 4095;
        const float4 v = (k0 < H)
            ? *(const float4*)&W_ih[row * H + k0]
            : *(const float4*)&W_hh[row * H + (k0 - H)];
        union { __half2 h; unsigned u; } a, b;
        a.h = __floats2half2_rn(v.x, v.y);
        b.h = __floats2half2_rn(v.z, v.w);
        dst[i] = make_uint2(a.u, b.u);
    }
}

// ===========================================================================
// Kernel 1: persistent controller. 2048 warps; warp owns gate column n=gw.
// Per cell: fused GEMV over [W_ih|W_hh] (4 fp16 streams of 8KB, L2-resident)
// against smem [e|h], LSTM pointwise, grid barrier, stage h, distributed
// decode + argmax, stage next e.
// ===========================================================================
__global__ __launch_bounds__(NTHR, 1)
void controller_main(const float* __restrict__ b_ih,
                     const float* __restrict__ b_hh,
                     const float* __restrict__ enc_act,
                     const float* __restrict__ enc_block,
                     const float* __restrict__ dec_act,
                     const float* __restrict__ dec_block,
                     float* __restrict__ out)
{
    __shared__ float xe_sm[H2X];        // [0:2048)=e (fp32), [2048:4096)=h
    __shared__ float dec_sm[NBK - 1];

    const int tid  = threadIdx.x;
    const int lane = tid & 31;
    const int wid  = tid >> 5;
    const int gw   = blockIdx.x * NWARP_M + wid;

    // biases for this gate column (read once)
    float bsum[4];
    #pragma unroll
    for (int g = 0; g < 4; g++) bsum[g] = b_ih[g * H + gw] + b_hh[g * H + gw];

    // fused weight row pointers (8 KB fp16 each = 512 uint4)
    const uint4* wp0 = (const uint4*)(g_wc + ((size_t)(0 * H + gw)) * H2X);
    const uint4* wp1 = (const uint4*)(g_wc + ((size_t)(1 * H + gw)) * H2X);
    const uint4* wp2 = (const uint4*)(g_wc + ((size_t)(2 * H + gw)) * H2X);
    const uint4* wp3 = (const uint4*)(g_wc + ((size_t)(3 * H + gw)) * H2X);

    float cloc = 0.f;
    int   idx  = 0;
    unsigned gen = 0;

    for (int cell = 0; cell < 2 * NBK - 1; cell++) {
        const int wbuf = cell & 1;

        // fused GEMV (xe_sm staged at end of previous cell); cell 0: x=h=0
        float4 acc = make_float4(0.f, 0.f, 0.f, 0.f);
        if (cell > 0) {
            const float4* xp = (const float4*)xe_sm;
            #pragma unroll 4
            for (int j = lane; j < H2X / 8; j += 32) {   // 16 iters
                const float4 xa = xp[2 * j], xb = xp[2 * j + 1];
                const uint4 a0 = wp0[j], a1 = wp1[j], a2 = wp2[j], a3 = wp3[j];
                acc.x += dot8(a0, xa, xb);
                acc.y += dot8(a1, xa, xb);
                acc.z += dot8(a2, xa, xb);
                acc.w += dot8(a3, xa, xb);
            }
        }
        acc.x = wred(acc.x); acc.y = wred(acc.y);
        acc.z = wred(acc.z); acc.w = wred(acc.w);

        const float gi = acc.x + bsum[0];
        const float gf = acc.y + bsum[1];
        const float gg = acc.z + bsum[2];
        const float go = acc.w + bsum[3];

        const float c2 = sigf(gf) * cloc + sigf(gi) * tanhf(gg);
        const float h2 = sigf(go) * tanhf(c2);
        cloc = c2;
        if (lane == 0) {
            g_hbuf[wbuf][gw] = h2;
            if (cell == 2 * NBK - 2) g_cbuf[gw] = c2;
        }
        gen++;
        grid_sync_flags(gen);

        // stage new h into xe_sm[2048:] (L1-bypassing; other SMs wrote it)
        ((float4*)(xe_sm + H))[tid] = __ldcv((const float4*)g_hbuf[wbuf] + tid); // NTHR==H4
        __syncthreads();

        // distributed decode: warp j computes class j's logit against h
        const float* dec; int ncls;
        if (cell == 0) { dec = dec_act; ncls = 4; }
        else {
            const int bid = (cell + 1) >> 1;
            if (cell & 1) { dec = dec_block + (size_t)(bid - 1) * (NBK - 1) * H; ncls = bid; }
            else          { dec = dec_act   + (size_t)bid * 4 * H;               ncls = 4;   }
        }
        if (wid < ncls) {
            const float4* dr = (const float4*)(dec + (size_t)wid * H);
            const float4* hp = (const float4*)(xe_sm + H);
            float s = 0.f;
            #pragma unroll 4
            for (int j = lane; j < H4; j += 32) {
                const float4 d = dr[j], hv = hp[j];
                s += d.x*hv.x + d.y*hv.y + d.z*hv.z + d.w*hv.w;
            }
            s = wred(s);
            if (lane == 0) dec_sm[wid] = s;
        }
        __syncthreads();
        float best = dec_sm[0]; int bi = 0;
        for (int j = 1; j < ncls; j++) { float v = dec_sm[j]; if (v > best) { best = v; bi = j; } }
        idx = bi;

        // stage next cell's embedding e into xe_sm[0:2048) (fp32)
        if (cell + 1 < 2 * NBK - 1) {
            const int ncell = cell + 1;
            const int nbid  = (ncell + 1) >> 1;
            const float* emb = (ncell & 1)
                ? enc_act   + ((size_t)(nbid - 1) * 4         + idx) * H
                : enc_block + ((size_t)(nbid - 1) * (NBK - 1) + idx) * H;
            ((float4*)xe_sm)[tid] = __ldg((const float4*)emb + tid);   // NTHR==H4
        }
        __syncthreads();
    }

    // stage final c into xe_sm[0:2048) (e region no longer needed)
    ((float4*)xe_sm)[tid] = __ldcv((const float4*)g_cbuf + tid);
    __syncthreads();

    // replicate outputs to all 1024 (identical) batch rows
    if (blockIdx.x == 0) {
        const float idxf = (float)idx;
        for (int i = tid; i < BSZ; i += NTHR) out[i] = idxf;
    }
    float4* outh = (float4*)(out + BSZ);
    float4* outc = (float4*)(out + BSZ + (size_t)BSZ * H);
    const float4* hfin = (const float4*)(xe_sm + H);
    const float4* cfin = (const float4*)xe_sm;
    for (int r = blockIdx.x; r < BSZ; r += NCTA) {
        const size_t ro = (size_t)r * H4;
        for (int i = tid; i < H4; i += NTHR) {
            outh[ro + i] = hfin[i];
            outc[ro + i] = cfin[i];
        }
    }
}

extern "C" void kernel_launch(void* const* d_in, const int* in_sizes, int n_in,
                              void* d_out, int out_size) {
    // metadata order: inputs, W_ih, W_hh, b_ih, b_hh, enc_act, enc_block, dec_act, dec_block
    const float* W_ih      = (const float*)d_in[1];
    const float* W_hh      = (const float*)d_in[2];
    const float* b_ih      = (const float*)d_in[3];
    const float* b_hh      = (const float*)d_in[4];
    const float* enc_act   = (const float*)d_in[5];
    const float* enc_block = (const float*)d_in[6];
    const float* dec_act   = (const float*)d_in[7];
    const float* dec_block = (const float*)d_in[8];
    float* out = (float*)d_out;

    convert_weights<<<1024, 256>>>(W_ih, W_hh);
    controller_main<<<NCTA, NTHR>>>(b_ih, b_hh, enc_act, enc_block,
                                    dec_act, dec_block, out);
}

// round 6
// speedup vs baseline: 3.2451x; 1.1457x over previous
#include <cuda_runtime.h>
#include <cuda_fp16.h>
#include <math.h>

// ---------------------------------------------------------------------------
// ControllerLSTM on GB300, round 5.
// Kept: batch collapse (B=1), fused fp16 [W_ih|W_hh] weights (L2-resident),
// persistent main kernel, flag grid barrier.
// New: warp-specialized pipeline. 32 warps/CTA; warp pair (w, w+16) owns one
// gate column. Phase 1: hh-warp runs Whh*h while ih-warps decode h and stage
// the chosen embedding (decode off the critical path). Phase 2: both warps
// split Wih*e. Halved dependency chains + 2x warps for latency hiding.
// ---------------------------------------------------------------------------

#define H    2048
#define H2X  (2*H)
#define H4   (H/4)
#define BSZ  1024
#define NBK  12

#define NCTA  128
#define NTHR  1024
#define NWPH  16            // warp pairs per CTA = columns per CTA

__device__ __half g_wc[(size_t)4 * H * H2X];   // 67.1 MB fused fp16 weights
__device__ float  g_hbuf[2][H];
__device__ float  g_cbuf[H];

#define FLAG_STRIDE 8
__device__ volatile unsigned g_arrive[NCTA * FLAG_STRIDE];
__device__ volatile unsigned g_release;

__device__ __forceinline__ void grid_sync_flags(unsigned gen) {
    __syncthreads();
    const int tid = threadIdx.x;
    if (blockIdx.x == 0) {
        if (tid == 0) { __threadfence(); g_arrive[0] = gen; }
        if (tid < NCTA) {
            while (g_arrive[tid * FLAG_STRIDE] != gen) { }
        }
        __syncthreads();
        if (tid == 0) { __threadfence(); g_release = gen; }
    } else {
        if (tid == 0) {
            __threadfence();
            g_arrive[blockIdx.x * FLAG_STRIDE] = gen;
            while (g_release != gen) { }
        }
    }
    __syncthreads();
}

__device__ __forceinline__ float wred(float v) {
    #pragma unroll
    for (int o = 16; o > 0; o >>= 1) v += __shfl_xor_sync(0xffffffffu, v, o);
    return v;
}

__device__ __forceinline__ float sigf(float x) { return 1.0f / (1.0f + expf(-x)); }

__device__ __forceinline__ float dot8(uint4 w, float4 xa, float4 xb) {
    union { unsigned u; __half2 h; } c0, c1, c2, c3;
    c0.u = w.x; c1.u = w.y; c2.u = w.z; c3.u = w.w;
    const float2 f0 = __half22float2(c0.h);
    const float2 f1 = __half22float2(c1.h);
    const float2 f2 = __half22float2(c2.h);
    const float2 f3 = __half22float2(c3.h);
    return f0.x*xa.x + f0.y*xa.y + f1.x*xa.z + f1.y*xa.w
         + f2.x*xb.x + f2.y*xb.y + f3.x*xb.z + f3.y*xb.w;
}

#define IH_BAR() asm volatile("bar.sync 1, 512;" ::: "memory")

// decode params for hidden state produced by cell s
__device__ __forceinline__ void dec_params(int s, const float* dec_act,
                                           const float* dec_block,
                                           const float** dec, int* ncls) {
    if (s == 0) { *dec = dec_act; *ncls = 4; }
    else if (s & 1) { int bid = (s + 1) >> 1; *dec = dec_block + (size_t)(bid - 1) * (NBK - 1) * H; *ncls = bid; }
    else            { int bid = s >> 1;       *dec = dec_act   + (size_t)bid * 4 * H;               *ncls = 4; }
}

// ===========================================================================
// Kernel 0: fused fp16 conversion, uint4 (8-half) stores.
// ===========================================================================
__global__ __launch_bounds__(256, 2)
void convert_weights(const float* __restrict__ W_ih, const float* __restrict__ W_hh)
{
    const size_t n = (size_t)4 * H * H2X / 8;       // uint4 chunks
    const size_t stride = (size_t)gridDim.x * blockDim.x;
    uint4* __restrict__ dst = (uint4*)g_wc;
    for (size_t i = blockIdx.x * blockDim.x + threadIdx.x; i < n; i += stride) {
        const size_t o   = i * 8;
        const size_t row = o >> 12;
        const size_t k0  = o & 4095;
        const float* src = (k0 < H) ? (W_ih + row * H + k0) : (W_hh + row * H + (k0 - H));
        const float4 v0 = *(const float4*)src;
        const float4 v1 = *(const float4*)(src + 4);
        union { __half2 h; unsigned u; } a, b, c, d;
        a.h = __floats2half2_rn(v0.x, v0.y);
        b.h = __floats2half2_rn(v0.z, v0.w);
        c.h = __floats2half2_rn(v1.x, v1.y);
        d.h = __floats2half2_rn(v1.z, v1.w);
        dst[i] = make_uint4(a.u, b.u, c.u, d.u);
    }
}

// ===========================================================================
// Kernel 1: persistent controller, warp-specialized.
// ===========================================================================
__global__ __launch_bounds__(NTHR, 1)
void controller_main(const float* __restrict__ b_ih,
                     const float* __restrict__ b_hh,
                     const float* __restrict__ enc_act,
                     const float* __restrict__ enc_block,
                     const float* __restrict__ dec_act,
                     const float* __restrict__ dec_block,
                     float* __restrict__ out)
{
    __shared__ float xe_sm[H2X];          // [0:2048)=e, [2048:4096)=h  (16 KB)
    __shared__ float dec_sm[NBK - 1];
    __shared__ float psum_hh[NWPH][4];
    __shared__ float psum_p2[NWPH][4];
    __shared__ int   idx_final;

    const int tid  = threadIdx.x;
    const int lane = tid & 31;
    const int wid  = tid >> 5;
    const int w    = wid & (NWPH - 1);         // column slot in CTA
    const bool ih  = (wid < NWPH);             // ih-duty warps = threads 0..511
    const int gw   = blockIdx.x * NWPH + w;    // gate column

    float bsum[4];
    #pragma unroll
    for (int g = 0; g < 4; g++) bsum[g] = b_ih[g * H + gw] + b_hh[g * H + gw];

    const uint4* wp[4];
    #pragma unroll
    for (int g = 0; g < 4; g++)
        wp[g] = (const uint4*)(g_wc + ((size_t)(g * H + gw)) * H2X);

    float cloc = 0.f;          // meaningful on ih lane 0
    int   idx  = 0;            // ih warps
    unsigned gen = 0;

    for (int cell = 0; cell < 2 * NBK - 1; cell++) {
        if (cell == 0) {
            // x=0, h=0 -> gates are pure biases
            if (ih && lane == 0) {
                const float c2 = sigf(bsum[0]) * tanhf(bsum[2]);
                const float h2 = sigf(bsum[3]) * tanhf(c2);
                cloc = c2;
                g_hbuf[0][gw] = h2;
            }
        } else {
            // ---- stage h_{cell-1} ----
            if (tid < H4)
                ((float4*)(xe_sm + H))[tid] =
                    __ldcv((const float4*)g_hbuf[(cell - 1) & 1] + tid);
            __syncthreads();

            const float4* xp = (const float4*)xe_sm;

            if (ih) {
                // ---- phase 1 (ih): decode h_{cell-1}, stage e_cell ----
                const float* dec; int ncls;
                dec_params(cell - 1, dec_act, dec_block, &dec, &ncls);
                if (w < ncls) {
                    const float4* dr = (const float4*)(dec + (size_t)w * H);
                    const float4* hp = (const float4*)(xe_sm + H);
                    float s = 0.f;
                    #pragma unroll 4
                    for (int j = lane; j < H4; j += 32) {
                        const float4 d = dr[j], hv = hp[j];
                        s += d.x*hv.x + d.y*hv.y + d.z*hv.z + d.w*hv.w;
                    }
                    s = wred(s);
                    if (lane == 0) dec_sm[w] = s;
                }
                IH_BAR();
                float best = dec_sm[0]; int bi = 0;
                for (int j = 1; j < ncls; j++) { float v = dec_sm[j]; if (v > best) { best = v; bi = j; } }
                idx = bi;
                const int bid = (cell + 1) >> 1;
                const float* emb = (cell & 1)
                    ? enc_act   + ((size_t)(bid - 1) * 4         + idx) * H
                    : enc_block + ((size_t)(bid - 1) * (NBK - 1) + idx) * H;
                ((float4*)xe_sm)[tid] = __ldg((const float4*)emb + tid);  // tid<512 == H4/... (512 thr * 1 f4 = 2048 fl)
            } else {
                // ---- phase 1 (hh): Whh * h  (fused k in [2048,4096) -> uint4 j in [256,512)) ----
                float4 acc = make_float4(0.f, 0.f, 0.f, 0.f);
                #pragma unroll 2
                for (int j = 256 + lane; j < 512; j += 32) {
                    const float4 xa = xp[2 * j], xb = xp[2 * j + 1];
                    acc.x += dot8(wp[0][j], xa, xb);
                    acc.y += dot8(wp[1][j], xa, xb);
                    acc.z += dot8(wp[2][j], xa, xb);
                    acc.w += dot8(wp[3][j], xa, xb);
                }
                acc.x = wred(acc.x); acc.y = wred(acc.y);
                acc.z = wred(acc.z); acc.w = wred(acc.w);
                if (lane == 0) {
                    psum_hh[w][0] = acc.x; psum_hh[w][1] = acc.y;
                    psum_hh[w][2] = acc.z; psum_hh[w][3] = acc.w;
                }
            }
            __syncthreads();   // (A): e staged, psum_hh ready

            // ---- phase 2: Wih * e split between the pair ----
            {
                const int j0 = ih ? 0 : 128;
                float4 acc = make_float4(0.f, 0.f, 0.f, 0.f);
                #pragma unroll 2
                for (int j = j0 + lane; j < j0 + 128; j += 32) {
                    const float4 xa = xp[2 * j], xb = xp[2 * j + 1];
                    acc.x += dot8(wp[0][j], xa, xb);
                    acc.y += dot8(wp[1][j], xa, xb);
                    acc.z += dot8(wp[2][j], xa, xb);
                    acc.w += dot8(wp[3][j], xa, xb);
                }
                acc.x = wred(acc.x); acc.y = wred(acc.y);
                acc.z = wred(acc.z); acc.w = wred(acc.w);
                if (!ih) {
                    if (lane == 0) {
                        psum_p2[w][0] = acc.x; psum_p2[w][1] = acc.y;
                        psum_p2[w][2] = acc.z; psum_p2[w][3] = acc.w;
                    }
                } else if (lane == 0) {
                    // stash own partial for after sync
                    psum_hh[w][0] += acc.x; psum_hh[w][1] += acc.y;   // safe: hh warp done writing
                    psum_hh[w][2] += acc.z; psum_hh[w][3] += acc.w;
                }
            }
            __syncthreads();   // (B): all partials ready

            if (ih && lane == 0) {
                const float gi = psum_hh[w][0] + psum_p2[w][0] + bsum[0];
                const float gf = psum_hh[w][1] + psum_p2[w][1] + bsum[1];
                const float gg = psum_hh[w][2] + psum_p2[w][2] + bsum[2];
                const float go = psum_hh[w][3] + psum_p2[w][3] + bsum[3];
                const float c2 = sigf(gf) * cloc + sigf(gi) * tanhf(gg);
                const float h2 = sigf(go) * tanhf(c2);
                cloc = c2;
                g_hbuf[cell & 1][gw] = h2;
                if (cell == 2 * NBK - 2) g_cbuf[gw] = c2;
            }
        }
        gen++;
        grid_sync_flags(gen);
    }

    // ---- epilogue: decode h_22 for the output idx ----
    if (tid < H4)
        ((float4*)(xe_sm + H))[tid] = __ldcv((const float4*)g_hbuf[0] + tid); // cell 22 -> buf 0
    __syncthreads();
    if (ih) {
        const float* dec; int ncls;
        dec_params(2 * NBK - 2, dec_act, dec_block, &dec, &ncls);
        if (w < ncls) {
            const float4* dr = (const float4*)(dec + (size_t)w * H);
            const float4* hp = (const float4*)(xe_sm + H);
            float s = 0.f;
            #pragma unroll 4
            for (int j = lane; j < H4; j += 32) {
                const float4 d = dr[j], hv = hp[j];
                s += d.x*hv.x + d.y*hv.y + d.z*hv.z + d.w*hv.w;
            }
            s = wred(s);
            if (lane == 0) dec_sm[w] = s;
        }
        IH_BAR();
        if (wid == 0 && lane == 0) {
            float best = dec_sm[0]; int bi = 0;
            for (int j = 1; j < ncls; j++) { float v = dec_sm[j]; if (v > best) { best = v; bi = j; } }
            idx_final = bi;
        }
    }
    // stage final c into e-region
    if (tid < H4)
        ((float4*)xe_sm)[tid] = __ldcv((const float4*)g_cbuf + tid);
    __syncthreads();

    // ---- replicate outputs ----
    if (blockIdx.x == 0) {
        const float idxf = (float)idx_final;
        for (int i = tid; i < BSZ; i += NTHR) out[i] = idxf;
    }
    float4* outh = (float4*)(out + BSZ);
    float4* outc = (float4*)(out + BSZ + (size_t)BSZ * H);
    const float4* hfin = (const float4*)(xe_sm + H);
    const float4* cfin = (const float4*)xe_sm;
    for (int r = blockIdx.x; r < BSZ; r += NCTA) {
        const size_t ro = (size_t)r * H4;
        for (int i = tid; i < H4; i += NTHR) {
            outh[ro + i] = hfin[i];
            outc[ro + i] = cfin[i];
        }
    }
}

extern "C" void kernel_launch(void* const* d_in, const int* in_sizes, int n_in,
                              void* d_out, int out_size) {
    // metadata order: inputs, W_ih, W_hh, b_ih, b_hh, enc_act, enc_block, dec_act, dec_block
    const float* W_ih      = (const float*)d_in[1];
    const float* W_hh      = (const float*)d_in[2];
    const float* b_ih      = (const float*)d_in[3];
    const float* b_hh      = (const float*)d_in[4];
    const float* enc_act   = (const float*)d_in[5];
    const float* enc_block = (const float*)d_in[6];
    const float* dec_act   = (const float*)d_in[7];
    const float* dec_block = (const float*)d_in[8];
    float* out = (float*)d_out;

    convert_weights<<<2048, 256>>>(W_ih, W_hh);
    controller_main<<<NCTA, NTHR>>>(b_ih, b_hh, enc_act, enc_block,
                                    dec_act, dec_block, out);
}